// round 16
// baseline (speedup 1.0000x reference)
#include <cuda_runtime.h>
#include <cuda_bf16.h>

// ---------------- problem constants (1,3,224,224) ----------------
#define HH    224
#define WW    224
#define NPIX  (HH * WW)
#define WSR   10
#define KK    21            // 2*WSR+1

#define EPSF  1e-6f
#define EPS08 1.5848931924611134e-05f     // (1e-6)^0.8
#define C_LW  (-72.134752044448169f)      // -SIG_COLOR * log2(e)
#define SIG_SPACE_F (1.0f / 98.0f)        // 1/(7*7*2)
#define LOG2E 1.4426950408889634f
#define C1F   10.0f
#define C2F   5.0f

// ---------------- tiling ----------------
#define TX    32
#define TY    4
#define NZ    4
#define NTHR  (TX * TY * NZ)     // 512
#define RR    (TY + WSR)         // 14 halo rows (forward offsets: dy in [0,10])
#define CC    (TX + 2 * WSR)     // 52 halo cols
#define RC    (RR * CC)          // 728
#define GXB   (WW / TX)          // 7
#define GYB   (HH / TY)          // 56
#define NBLK  (GXB * GYB)        // 392

// ---------------- scratch (device globals: no allocation) ----------------
__device__ float    g_mask[NPIX];     // +1 = use_large, -1 = small branch
__device__ float    g_part[NBLK];     // per-block partial sums
__device__ unsigned g_counter = 0;    // last-block detector (reset each call)

// MUFU wrappers
__device__ __forceinline__ float ex2f(float x) {
    float y; asm("ex2.approx.f32 %0, %1;" : "=f"(y) : "f"(x)); return y;
}
__device__ __forceinline__ float lg2f(float x) {
    float y; asm("lg2.approx.f32 %0, %1;" : "=f"(y) : "f"(x)); return y;
}
// wr * t^0.8 fused: exp2(0.8*log2(t) + lw), lw = C_LW * cd
__device__ __forceinline__ float powterm(float t, float lw) {
    return ex2f(fmaf(0.8f, lg2f(t), lw));
}

// ============================================================================
// Pass 1: per-pixel branch mask (unchanged — fast).
// ============================================================================
__global__ __launch_bounds__(128) void mask_kernel(
    const float* __restrict__ orig, const float* __restrict__ smv)
{
    const int p = blockIdx.x * 128 + threadIdx.x;    // NPIX == 392*128 exactly
    const int y = p / WW, x = p - y * WW;

    const float oc0 = orig[p], oc1 = orig[NPIX + p], oc2 = orig[2 * NPIX + p];
    const bool xin = (x >= WSR) && (x < WW - WSR);

    float ero = 0.0f;
    #pragma unroll 1
    for (int dy = -WSR; dy <= WSR; ++dy) {
        int yy = y + dy;
        if ((unsigned)yy >= (unsigned)HH) continue;
        const float* r = orig + yy * WW;
        float rs = 0.0f;
        if (xin) {
            #pragma unroll
            for (int dx = -WSR; dx <= WSR; ++dx) {
                int q = x + dx;
                float o0 = r[q], o1 = r[NPIX + q], o2 = r[2 * NPIX + q];
                rs += (o0 > 0.0f) ? fabsf(o0 - oc0) : 0.0f;
                rs += (o1 > 0.0f) ? fabsf(o1 - oc1) : 0.0f;
                rs += (o2 > 0.0f) ? fabsf(o2 - oc2) : 0.0f;
            }
        } else {
            #pragma unroll
            for (int dx = -WSR; dx <= WSR; ++dx) {
                int xx = x + dx;
                bool v = (unsigned)xx < (unsigned)WW;
                int q = v ? xx : x;
                float o0 = r[q], o1 = r[NPIX + q], o2 = r[2 * NPIX + q];
                rs += (v && o0 > 0.0f) ? fabsf(o0 - oc0) : 0.0f;
                rs += (v && o1 > 0.0f) ? fabsf(o1 - oc1) : 0.0f;
                rs += (v && o2 > 0.0f) ? fabsf(o2 - oc2) : 0.0f;
            }
        }
        ero += rs;
        if (ero >= C1F) break;   // terms non-negative: final er_o >= partial
    }

    bool useL = false;
    if (ero < C1F) {
        float sc0 = smv[p], sc1 = smv[NPIX + p], sc2 = smv[2 * NPIX + p];
        float ers = 0.0f;
        int xlo = max(x - WSR, 0), xhi = min(x + WSR, WW - 1);
        int ylo = max(y - WSR, 0), yhi = min(y + WSR, HH - 1);
        for (int yy = ylo; yy <= yhi; ++yy) {
            int rowb = yy * WW;
            for (int xx = xlo; xx <= xhi; ++xx) {
                int q = rowb + xx;
                float s0 = smv[q], s1 = smv[NPIX + q], s2 = smv[2 * NPIX + q];
                ers += (s0 > 0.0f) ? fabsf(s0 - sc0) : 0.0f;
                ers += (s1 > 0.0f) ? fabsf(s1 - sc1) : 0.0f;
                ers += (s2 > 0.0f) ? fabsf(s2 - sc2) : 0.0f;
            }
        }
        useL = (ers - ero) > C2F;
    }
    g_mask[p] = useL ? 1.0f : -1.0f;
}

// ============================================================================
// Pass 2: forward-offset 4-way balanced split (55 pairs per z):
//   z0: dy=0 dx 1..5   + dy 1..10 dx -10..-6
//   z1: dy=0 dx 6..10  + dy 1..10 dx -5..-1
//   z2: dy 1..10 dx 0..4  + dy 1..5  dx 5
//   z3: dy 1..10 dx 6..10 + dy 6..10 dx 5
// Shared tiles are SCALAR planes (conflict-free 1-phase LDS.32).
// ============================================================================

// FAST: no use_large anywhere, all in-bounds s>0. EDGEV: halo may be OOB
// (zeroed, v=0); pair weight w = -2*v_j in {2,0}. Full-window OOB analytic
// (z==0 thread only).
template <bool EDGEV, int Z>
__device__ __forceinline__ float window_fast(
    const float* __restrict__ ssp, const float* __restrict__ osp,
    const float* __restrict__ vsp, int base, int gx, int gy)
{
    const float si0 = ssp[base], si1 = ssp[RC + base], si2 = ssp[2 * RC + base];
    const float oi0 = osp[base], oi1 = osp[RC + base], oi2 = osp[2 * RC + base];

    float acc = 0.0f;
    if (Z == 0) {
        int ninx = min(gx, WSR) + min(WW - 1 - gx, WSR) + 1;
        int niny = min(gy, WSR) + min(HH - 1 - gy, WSR) + 1;
        float noob = (float)(KK * KK - ninx * niny);
        float cdo  = fmaf(oi0, oi0, fmaf(oi1, oi1, oi2 * oi2));
        acc = (3.0f * EPS08) * fmaf(noob, ex2f(C_LW * cdo), 1.0f);
    }

    auto pair = [&](int off) {
        float sj0 = ssp[off], sj1 = ssp[RC + off], sj2 = ssp[2 * RC + off];
        float oj0 = osp[off], oj1 = osp[RC + off], oj2 = osp[2 * RC + off];
        float d0 = oj0 - oi0, d1 = oj1 - oi1, d2 = oj2 - oi2;
        float lw = fmaf(d0, d0, fmaf(d1, d1, d2 * d2)) * C_LW;
        float t0 = fabsf(sj0 - si0) + EPSF;
        float t1 = fabsf(sj1 - si1) + EPSF;
        float t2 = fabsf(sj2 - si2) + EPSF;
        float p = powterm(t0, lw) + powterm(t1, lw) + powterm(t2, lw);
        if (EDGEV) acc = fmaf(-2.0f * vsp[off], p, acc);
        else       acc = fmaf(2.0f, p, acc);
    };

    if (Z == 0) {
        #pragma unroll
        for (int dx = 1; dx <= 5; ++dx) pair(base + dx);
        #pragma unroll 1
        for (int dy = 1; dy <= WSR; ++dy) {
            int rb = base + dy * CC;
            #pragma unroll
            for (int dx = -10; dx <= -6; ++dx) pair(rb + dx);
        }
    } else if (Z == 1) {
        #pragma unroll
        for (int dx = 6; dx <= 10; ++dx) pair(base + dx);
        #pragma unroll 1
        for (int dy = 1; dy <= WSR; ++dy) {
            int rb = base + dy * CC;
            #pragma unroll
            for (int dx = -5; dx <= -1; ++dx) pair(rb + dx);
        }
    } else if (Z == 2) {
        #pragma unroll 1
        for (int dy = 1; dy <= WSR; ++dy) {
            int rb = base + dy * CC;
            #pragma unroll
            for (int dx = 0; dx <= 4; ++dx) pair(rb + dx);
        }
        #pragma unroll
        for (int dy = 1; dy <= 5; ++dy) pair(base + dy * CC + 5);
    } else {
        #pragma unroll 1
        for (int dy = 1; dy <= WSR; ++dy) {
            int rb = base + dy * CC;
            #pragma unroll
            for (int dx = 6; dx <= 10; ++dx) pair(rb + dx);
        }
        #pragma unroll
        for (int dy = 6; dy <= 10; ++dy) pair(base + dy * CC + 5);
    }
    return acc;
}

// SAFE: branch-free select body (handles exact-zero samples and use_large).
// Backward-OOB analytic (z==0 only); forward-OOB via halo zeros.
template <bool LARGE, int Z>
__device__ __forceinline__ float window_safe(
    const float* __restrict__ ssp, const float* __restrict__ osp,
    const float* __restrict__ vsp, const float* __restrict__ ws1d,
    int base, int gx, int gy)
{
    const float si0 = ssp[base], si1 = ssp[RC + base], si2 = ssp[2 * RC + base];
    const float oi0 = osp[base], oi1 = osp[RC + base], oi2 = osp[2 * RC + base];
    float wLi = 0.0f, wSi = 1.0f;
    if (LARGE) {
        float vi = vsp[base];
        wLi = fmaxf(vi, 0.0f); wSi = fmaxf(-vi, 0.0f);
    }
    const bool pi0 = (si0 > 0.0f), pi1 = (si1 > 0.0f), pi2 = (si2 > 0.0f);

    float acc = 0.0f;
    if (Z == 0) {
        int left  = max(WSR - gx, 0);
        int right = max(gx - (WW - 1 - WSR), 0);
        int up    = max(WSR - gy, 0);
        int inRowsBack = min(gy, WSR);
        float noob = (float)(left * (1 + inRowsBack) + KK * up + right * inRowsBack);
        float cdo  = fmaf(oi0, oi0, fmaf(oi1, oi1, oi2 * oi2));
        acc = wSi * (3.0f * EPS08) * fmaf(noob, ex2f(C_LW * cdo), 1.0f);
    }

    auto pair = [&](int off, float aw) {
        float sj0 = ssp[off], sj1 = ssp[RC + off], sj2 = ssp[2 * RC + off];
        float oj0 = osp[off], oj1 = osp[RC + off], oj2 = osp[2 * RC + off];
        float vj  = vsp[off];
        float d0 = oj0 - oi0, d1 = oj1 - oi1, d2 = oj2 - oi2;
        float lw = fmaf(d0, d0, fmaf(d1, d1, d2 * d2)) * C_LW;
        float e0 = sj0 - si0, e1 = sj1 - si1, e2 = sj2 - si2;
        float pt0 = powterm(fabsf(e0) + EPSF, lw);
        float pt1 = powterm(fabsf(e1) + EPSF, lw);
        float pt2 = powterm(fabsf(e2) + EPSF, lw);
        float ew  = EPS08 * ex2f(lw);                  // wr * eps^0.8
        bool  pj0 = (sj0 > 0.0f), pj1 = (sj1 > 0.0f), pj2 = (sj2 > 0.0f);
        float pA = (pj0 ? pt0 : ew) + (pj1 ? pt1 : ew) + (pj2 ? pt2 : ew);
        float pB = (pi0 ? pt0 : ew) + (pi1 ? pt1 : ew) + (pi2 ? pt2 : ew);
        float wSj = fmaxf(-vj, 0.0f);
        if (LARGE) {
            acc = fmaf(wSi, pA, fmaf(wSj, pB, acc));
            float q0 = e0 * e0, q1 = e1 * e1, q2 = e2 * e2;
            float QA = (pj0 ? q0 : 0.0f) + (pj1 ? q1 : 0.0f) + (pj2 ? q2 : 0.0f);
            float QB = (pi0 ? q0 : 0.0f) + (pi1 ? q1 : 0.0f) + (pi2 ? q2 : 0.0f);
            float wLj = fmaxf(vj, 0.0f);
            acc = fmaf(aw, fmaf(wLi, QA, wLj * QB), acc);
        } else {
            acc = fmaf(wSj, pB, acc + pA);   // wSi == 1 in all-small tile
        }
    };

    #define AW(dy, dx) (LARGE ? 5.0f * ws1d[WSR + (dy)] * ws1d[WSR + (dx)] : 0.0f)
    if (Z == 0) {
        #pragma unroll
        for (int dx = 1; dx <= 5; ++dx) pair(base + dx, AW(0, dx));
        #pragma unroll 1
        for (int dy = 1; dy <= WSR; ++dy) {
            int rb = base + dy * CC;
            #pragma unroll
            for (int dx = -10; dx <= -6; ++dx) pair(rb + dx, AW(dy, dx));
        }
    } else if (Z == 1) {
        #pragma unroll
        for (int dx = 6; dx <= 10; ++dx) pair(base + dx, AW(0, dx));
        #pragma unroll 1
        for (int dy = 1; dy <= WSR; ++dy) {
            int rb = base + dy * CC;
            #pragma unroll
            for (int dx = -5; dx <= -1; ++dx) pair(rb + dx, AW(dy, dx));
        }
    } else if (Z == 2) {
        #pragma unroll 1
        for (int dy = 1; dy <= WSR; ++dy) {
            int rb = base + dy * CC;
            #pragma unroll
            for (int dx = 0; dx <= 4; ++dx) pair(rb + dx, AW(dy, dx));
        }
        #pragma unroll
        for (int dy = 1; dy <= 5; ++dy) pair(base + dy * CC + 5, AW(dy, 5));
    } else {
        #pragma unroll 1
        for (int dy = 1; dy <= WSR; ++dy) {
            int rb = base + dy * CC;
            #pragma unroll
            for (int dx = 6; dx <= 10; ++dx) pair(rb + dx, AW(dy, dx));
        }
        #pragma unroll
        for (int dy = 6; dy <= 10; ++dy) pair(base + dy * CC + 5, AW(dy, 5));
    }
    #undef AW
    return acc;
}

__global__ __launch_bounds__(NTHR, 2) void loss_kernel(
    const float* __restrict__ orig, const float* __restrict__ smv,
    float* __restrict__ out)
{
    __shared__ float  ssm[3 * RC];
    __shared__ float  som[3 * RC];
    __shared__ float  svm[RC];
    __shared__ float  ws1d[KK];
    __shared__ int    s_hasL, s_hasZ, s_last;
    __shared__ float  red[NTHR];
    __shared__ double rd[NTHR];

    const int tid = (threadIdx.z * TY + threadIdx.y) * TX + threadIdx.x;
    if (tid == 0) { s_hasL = 0; s_hasZ = 0; s_last = 0; }
    if (tid < KK) {
        int d = tid - WSR;
        ws1d[tid] = ex2f(-SIG_SPACE_F * LOG2E * (float)(d * d));
    }

    const int x0 = blockIdx.x * TX, y0 = blockIdx.y * TY;

    int fL = 0, fZ = 0;
    for (int idx = tid; idx < RC; idx += NTHR) {
        int r = idx / CC, i = idx - r * CC;
        int gy = y0 + r, gx = x0 - WSR + i;
        float s0 = 0, s1 = 0, s2 = 0, o0 = 0, o1 = 0, o2 = 0, v = 0;
        if (gy < HH && (unsigned)gx < (unsigned)WW) {
            int gi = gy * WW + gx;
            s0 = smv[gi]; s1 = smv[NPIX + gi]; s2 = smv[2 * NPIX + gi];
            o0 = orig[gi]; o1 = orig[NPIX + gi]; o2 = orig[2 * NPIX + gi];
            v  = g_mask[gi];
            fZ |= (fminf(s0, fminf(s1, s2)) <= 0.0f) ? 1 : 0;  // in-bounds zeros
        }
        ssm[idx] = s0; ssm[RC + idx] = s1; ssm[2 * RC + idx] = s2;
        som[idx] = o0; som[RC + idx] = o1; som[2 * RC + idx] = o2;
        svm[idx] = v;
        fL |= (v > 0.0f) ? 1 : 0;
    }
    if (fL) s_hasL = 1;
    if (fZ) s_hasZ = 1;
    __syncthreads();

    const bool hasOOB = (blockIdx.x == 0) | (blockIdx.x == GXB - 1) | (y0 + RR > HH);
    const int gx = x0 + threadIdx.x, gy = y0 + threadIdx.y;
    const int base = threadIdx.y * CC + threadIdx.x + WSR;

    float acc;
    #define DISPATCH(ZV)                                                                 \
        if (s_hasL)      acc = window_safe<true , ZV>(ssm, som, svm, ws1d, base, gx, gy);\
        else if (s_hasZ) acc = window_safe<false, ZV>(ssm, som, svm, ws1d, base, gx, gy);\
        else if (hasOOB) acc = window_fast<true , ZV>(ssm, som, svm, base, gx, gy);      \
        else             acc = window_fast<false, ZV>(ssm, som, svm, base, gx, gy);
    if      (threadIdx.z == 0) { DISPATCH(0) }
    else if (threadIdx.z == 1) { DISPATCH(1) }
    else if (threadIdx.z == 2) { DISPATCH(2) }
    else                       { DISPATCH(3) }
    #undef DISPATCH

    red[tid] = acc;
    __syncthreads();
    #pragma unroll
    for (int s = NTHR / 2; s > 0; s >>= 1) {
        if (tid < s) red[tid] += red[tid + s];
        __syncthreads();
    }

    const int bid = blockIdx.y * gridDim.x + blockIdx.x;
    if (tid == 0) {
        g_part[bid] = red[0];
        __threadfence();
        unsigned old = atomicAdd(&g_counter, 1u);
        s_last = (old == (unsigned)(NBLK - 1)) ? 1 : 0;
    }
    __syncthreads();

    // Last block: deterministic fp64 finalize (fixed index order).
    if (s_last) {
        double s = 0.0;
        for (int i = tid; i < NBLK; i += NTHR) s += (double)__ldcg(&g_part[i]);
        rd[tid] = s;
        __syncthreads();
        #pragma unroll
        for (int k = NTHR / 2; k > 0; k >>= 1) {
            if (tid < k) rd[tid] += rd[tid + k];
            __syncthreads();
        }
        if (tid == 0) {
            const double scale = 1.0 / ((double)HH * (double)WW) / (double)(WSR * WSR);
            out[0] = (float)(rd[0] * scale);
            g_counter = 0;   // reset for next graph replay
        }
    }
}

extern "C" void kernel_launch(void* const* d_in, const int* in_sizes, int n_in,
                              void* d_out, int out_size)
{
    (void)in_sizes; (void)n_in; (void)out_size;
    const float* orig = (const float*)d_in[0];   // original_images (1,3,224,224)
    const float* smv  = (const float*)d_in[1];   // smooth_images   (1,3,224,224)
    float* out = (float*)d_out;

    mask_kernel<<<NPIX / 128, 128>>>(orig, smv);

    dim3 grid(GXB, GYB);
    dim3 blk(TX, TY, NZ);
    loss_kernel<<<grid, blk>>>(orig, smv, out);
}

// round 17
// speedup vs baseline: 1.2986x; 1.2986x over previous
#include <cuda_runtime.h>
#include <cuda_bf16.h>

// ---------------- problem constants (1,3,224,224) ----------------
#define HH    224
#define WW    224
#define NPIX  (HH * WW)
#define WSR   10
#define KK    21            // 2*WSR+1

#define EPSF  1e-6f
#define EPS08 1.5848931924611134e-05f     // (1e-6)^0.8
#define C_LW  (-72.134752044448169f)      // -SIG_COLOR * log2(e)
#define SIG_SPACE_F (1.0f / 98.0f)        // 1/(7*7*2)
#define LOG2E 1.4426950408889634f
#define C1F   10.0f
#define C2F   5.0f

// ---------------- tiling ----------------
#define TX    32
#define TY    4
#define NZ    2
#define NTHR  (TX * TY * NZ)     // 256
#define RR    (TY + WSR)         // 14 halo rows (forward offsets: dy in [0,10])
#define CC    (TX + 2 * WSR)     // 52 halo cols
#define RC    (RR * CC)          // 728
#define GXB   (WW / TX)          // 7
#define GYB   (HH / TY)          // 56
#define NBLK  (GXB * GYB)        // 392

// ---------------- scratch (device globals: no allocation) ----------------
__device__ float    g_mask[NPIX];     // +1 = use_large, -1 = small branch
__device__ float    g_part[NBLK];     // per-block partial sums
__device__ unsigned g_counter = 0;    // last-block detector (reset each call)

// MUFU wrappers
__device__ __forceinline__ float ex2f(float x) {
    float y; asm("ex2.approx.f32 %0, %1;" : "=f"(y) : "f"(x)); return y;
}
__device__ __forceinline__ float lg2f(float x) {
    float y; asm("lg2.approx.f32 %0, %1;" : "=f"(y) : "f"(x)); return y;
}
// wr * t^0.8 fused: exp2(0.8*log2(t) + lw), lw = C_LW * cd
__device__ __forceinline__ float powterm(float t, float lw) {
    return ex2f(fmaf(0.8f, lg2f(t), lw));
}

// ============================================================================
// Pass 1: per-pixel branch mask (unchanged — fast).
// ============================================================================
__global__ __launch_bounds__(128) void mask_kernel(
    const float* __restrict__ orig, const float* __restrict__ smv)
{
    const int p = blockIdx.x * 128 + threadIdx.x;    // NPIX == 392*128 exactly
    const int y = p / WW, x = p - y * WW;

    const float oc0 = orig[p], oc1 = orig[NPIX + p], oc2 = orig[2 * NPIX + p];
    const bool xin = (x >= WSR) && (x < WW - WSR);

    float ero = 0.0f;
    #pragma unroll 1
    for (int dy = -WSR; dy <= WSR; ++dy) {
        int yy = y + dy;
        if ((unsigned)yy >= (unsigned)HH) continue;
        const float* r = orig + yy * WW;
        float rs = 0.0f;
        if (xin) {
            #pragma unroll
            for (int dx = -WSR; dx <= WSR; ++dx) {
                int q = x + dx;
                float o0 = r[q], o1 = r[NPIX + q], o2 = r[2 * NPIX + q];
                rs += (o0 > 0.0f) ? fabsf(o0 - oc0) : 0.0f;
                rs += (o1 > 0.0f) ? fabsf(o1 - oc1) : 0.0f;
                rs += (o2 > 0.0f) ? fabsf(o2 - oc2) : 0.0f;
            }
        } else {
            #pragma unroll
            for (int dx = -WSR; dx <= WSR; ++dx) {
                int xx = x + dx;
                bool v = (unsigned)xx < (unsigned)WW;
                int q = v ? xx : x;
                float o0 = r[q], o1 = r[NPIX + q], o2 = r[2 * NPIX + q];
                rs += (v && o0 > 0.0f) ? fabsf(o0 - oc0) : 0.0f;
                rs += (v && o1 > 0.0f) ? fabsf(o1 - oc1) : 0.0f;
                rs += (v && o2 > 0.0f) ? fabsf(o2 - oc2) : 0.0f;
            }
        }
        ero += rs;
        if (ero >= C1F) break;   // terms non-negative: final er_o >= partial
    }

    bool useL = false;
    if (ero < C1F) {
        float sc0 = smv[p], sc1 = smv[NPIX + p], sc2 = smv[2 * NPIX + p];
        float ers = 0.0f;
        int xlo = max(x - WSR, 0), xhi = min(x + WSR, WW - 1);
        int ylo = max(y - WSR, 0), yhi = min(y + WSR, HH - 1);
        for (int yy = ylo; yy <= yhi; ++yy) {
            int rowb = yy * WW;
            for (int xx = xlo; xx <= xhi; ++xx) {
                int q = rowb + xx;
                float s0 = smv[q], s1 = smv[NPIX + q], s2 = smv[2 * NPIX + q];
                ers += (s0 > 0.0f) ? fabsf(s0 - sc0) : 0.0f;
                ers += (s1 > 0.0f) ? fabsf(s1 - sc1) : 0.0f;
                ers += (s2 > 0.0f) ? fabsf(s2 - sc2) : 0.0f;
            }
        }
        useL = (ers - ero) > C2F;
    }
    g_mask[p] = useL ? 1.0f : -1.0f;
}

// ============================================================================
// Pass 2: forward-offset 2-way split (110 pairs per z):
//   z0: {dy=0, dx=1..10} U {dy=1..10, dx=-10..-1}
//   z1: {dy=1..10, dx=0..10}
// Packed float2 shared planes: s01=(s0,s1), s2q=(s2, C_LW*sum(o^2)),
// o01=(o0,o1), o2v=(o2, v). 4 x LDS.64 per pair, conflict-free.
// lw = A_i + q_j + sum_k ci_k*oj_k with ci_k = -2*C_LW*oi_k (hoisted).
// OOB halo zeros (q=0) reproduce the reference's zero-padded wr exactly.
// ============================================================================

// FAST: no use_large anywhere, all in-bounds s>0. EDGEV: halo may be OOB
// (zeroed, v=0); pair weight w = -2*v_j in {2,0}. Full-window OOB analytic
// (z==0 thread only).
template <bool EDGEV, int Z>
__device__ __forceinline__ float window_fast(
    const float2* __restrict__ s01, const float2* __restrict__ s2q,
    const float2* __restrict__ o01, const float2* __restrict__ o2v,
    int base, int gx, int gy)
{
    const float2 a = s01[base], b = s2q[base];
    const float2 c = o01[base], d = o2v[base];
    const float si0 = a.x, si1 = a.y, si2 = b.x;
    const float Ai  = b.y;                          // C_LW * sum(oi^2)
    const float ci0 = -2.0f * C_LW * c.x;
    const float ci1 = -2.0f * C_LW * c.y;
    const float ci2 = -2.0f * C_LW * d.x;

    float acc = 0.0f;
    if (Z == 0) {
        int ninx = min(gx, WSR) + min(WW - 1 - gx, WSR) + 1;
        int niny = min(gy, WSR) + min(HH - 1 - gy, WSR) + 1;
        float noob = (float)(KK * KK - ninx * niny);
        acc = (3.0f * EPS08) * fmaf(noob, ex2f(Ai), 1.0f);
    }

    auto pair = [&](int off) {
        float2 sa = s01[off], sb = s2q[off];
        float2 oa = o01[off], ob = o2v[off];
        float lw = fmaf(ci0, oa.x, fmaf(ci1, oa.y, fmaf(ci2, ob.x, Ai + sb.y)));
        float t0 = fabsf(sa.x - si0) + EPSF;
        float t1 = fabsf(sa.y - si1) + EPSF;
        float t2 = fabsf(sb.x - si2) + EPSF;
        float p = powterm(t0, lw) + powterm(t1, lw) + powterm(t2, lw);
        if (EDGEV) acc = fmaf(-2.0f * ob.y, p, acc);
        else       acc = fmaf(2.0f, p, acc);
    };

    if (Z == 0) {
        #pragma unroll
        for (int dx = 1; dx <= WSR; ++dx) pair(base + dx);
        #pragma unroll 1
        for (int dy = 1; dy <= WSR; ++dy) {
            int rb = base + dy * CC;
            #pragma unroll
            for (int dx = -WSR; dx <= -1; ++dx) pair(rb + dx);
        }
    } else {
        #pragma unroll 1
        for (int dy = 1; dy <= WSR; ++dy) {
            int rb = base + dy * CC;
            #pragma unroll
            for (int dx = 0; dx <= WSR; ++dx) pair(rb + dx);
        }
    }
    return acc;
}

// SAFE: branch-free select body (handles exact-zero samples and use_large).
// Backward-OOB analytic (z==0 only); forward-OOB via halo zeros.
template <bool LARGE, int Z>
__device__ __forceinline__ float window_safe(
    const float2* __restrict__ s01, const float2* __restrict__ s2q,
    const float2* __restrict__ o01, const float2* __restrict__ o2v,
    const float* __restrict__ ws1d, int base, int gx, int gy)
{
    const float2 a = s01[base], b = s2q[base];
    const float2 c = o01[base], d = o2v[base];
    const float si0 = a.x, si1 = a.y, si2 = b.x;
    const float Ai  = b.y;
    const float ci0 = -2.0f * C_LW * c.x;
    const float ci1 = -2.0f * C_LW * c.y;
    const float ci2 = -2.0f * C_LW * d.x;
    float wLi = 0.0f, wSi = 1.0f;
    if (LARGE) {
        float vi = d.y;
        wLi = fmaxf(vi, 0.0f); wSi = fmaxf(-vi, 0.0f);
    }
    const bool pi0 = (si0 > 0.0f), pi1 = (si1 > 0.0f), pi2 = (si2 > 0.0f);

    float acc = 0.0f;
    if (Z == 0) {
        int left  = max(WSR - gx, 0);
        int right = max(gx - (WW - 1 - WSR), 0);
        int up    = max(WSR - gy, 0);
        int inRowsBack = min(gy, WSR);
        float noob = (float)(left * (1 + inRowsBack) + KK * up + right * inRowsBack);
        acc = wSi * (3.0f * EPS08) * fmaf(noob, ex2f(Ai), 1.0f);
    }

    auto pair = [&](int off, float aw) {
        float2 sa = s01[off], sb = s2q[off];
        float2 oa = o01[off], ob = o2v[off];
        float vj  = ob.y;
        float lw = fmaf(ci0, oa.x, fmaf(ci1, oa.y, fmaf(ci2, ob.x, Ai + sb.y)));
        float e0 = sa.x - si0, e1 = sa.y - si1, e2 = sb.x - si2;
        float pt0 = powterm(fabsf(e0) + EPSF, lw);
        float pt1 = powterm(fabsf(e1) + EPSF, lw);
        float pt2 = powterm(fabsf(e2) + EPSF, lw);
        float ew  = EPS08 * ex2f(lw);                  // wr * eps^0.8
        bool  pj0 = (sa.x > 0.0f), pj1 = (sa.y > 0.0f), pj2 = (sb.x > 0.0f);
        float pA = (pj0 ? pt0 : ew) + (pj1 ? pt1 : ew) + (pj2 ? pt2 : ew);
        float pB = (pi0 ? pt0 : ew) + (pi1 ? pt1 : ew) + (pi2 ? pt2 : ew);
        float wSj = fmaxf(-vj, 0.0f);
        if (LARGE) {
            acc = fmaf(wSi, pA, fmaf(wSj, pB, acc));
            float q0 = e0 * e0, q1 = e1 * e1, q2 = e2 * e2;
            float QA = (pj0 ? q0 : 0.0f) + (pj1 ? q1 : 0.0f) + (pj2 ? q2 : 0.0f);
            float QB = (pi0 ? q0 : 0.0f) + (pi1 ? q1 : 0.0f) + (pi2 ? q2 : 0.0f);
            float wLj = fmaxf(vj, 0.0f);
            acc = fmaf(aw, fmaf(wLi, QA, wLj * QB), acc);
        } else {
            acc = fmaf(wSj, pB, acc + pA);   // wSi == 1 in all-small tile
        }
    };

    #define AW(dy, dx) (LARGE ? 5.0f * ws1d[WSR + (dy)] * ws1d[WSR + (dx)] : 0.0f)
    if (Z == 0) {
        #pragma unroll
        for (int dx = 1; dx <= WSR; ++dx) pair(base + dx, AW(0, dx));
        #pragma unroll 1
        for (int dy = 1; dy <= WSR; ++dy) {
            int rb = base + dy * CC;
            #pragma unroll
            for (int dx = -WSR; dx <= -1; ++dx) pair(rb + dx, AW(dy, dx));
        }
    } else {
        #pragma unroll 1
        for (int dy = 1; dy <= WSR; ++dy) {
            int rb = base + dy * CC;
            #pragma unroll
            for (int dx = 0; dx <= WSR; ++dx) pair(rb + dx, AW(dy, dx));
        }
    }
    #undef AW
    return acc;
}

__global__ __launch_bounds__(NTHR) void loss_kernel(
    const float* __restrict__ orig, const float* __restrict__ smv,
    float* __restrict__ out)
{
    __shared__ float2 s01[RC];     // (s0, s1)
    __shared__ float2 s2q[RC];     // (s2, C_LW*sum(o^2))
    __shared__ float2 o01[RC];     // (o0, o1)
    __shared__ float2 o2v[RC];     // (o2, v)
    __shared__ float  ws1d[KK];
    __shared__ int    s_hasL, s_hasZ, s_last;
    __shared__ float  red[NTHR];
    __shared__ double rd[NTHR];

    const int tid = (threadIdx.z * TY + threadIdx.y) * TX + threadIdx.x;
    if (tid == 0) { s_hasL = 0; s_hasZ = 0; s_last = 0; }
    if (tid < KK) {
        int d = tid - WSR;
        ws1d[tid] = ex2f(-SIG_SPACE_F * LOG2E * (float)(d * d));
    }

    const int x0 = blockIdx.x * TX, y0 = blockIdx.y * TY;

    int fL = 0, fZ = 0;
    for (int idx = tid; idx < RC; idx += NTHR) {
        int r = idx / CC, i = idx - r * CC;
        int gy = y0 + r, gx = x0 - WSR + i;
        float s0 = 0, s1 = 0, s2 = 0, o0 = 0, o1 = 0, o2 = 0, v = 0;
        if (gy < HH && (unsigned)gx < (unsigned)WW) {
            int gi = gy * WW + gx;
            s0 = smv[gi]; s1 = smv[NPIX + gi]; s2 = smv[2 * NPIX + gi];
            o0 = orig[gi]; o1 = orig[NPIX + gi]; o2 = orig[2 * NPIX + gi];
            v  = g_mask[gi];
            fZ |= (fminf(s0, fminf(s1, s2)) <= 0.0f) ? 1 : 0;  // in-bounds zeros
        }
        float q = C_LW * fmaf(o0, o0, fmaf(o1, o1, o2 * o2));
        s01[idx] = make_float2(s0, s1);
        s2q[idx] = make_float2(s2, q);
        o01[idx] = make_float2(o0, o1);
        o2v[idx] = make_float2(o2, v);
        fL |= (v > 0.0f) ? 1 : 0;
    }
    if (fL) s_hasL = 1;
    if (fZ) s_hasZ = 1;
    __syncthreads();

    const bool hasOOB = (blockIdx.x == 0) | (blockIdx.x == GXB - 1) | (y0 + RR > HH);
    const int gx = x0 + threadIdx.x, gy = y0 + threadIdx.y;
    const int base = threadIdx.y * CC + threadIdx.x + WSR;

    float acc;
    #define DISPATCH(ZV)                                                                    \
        if (s_hasL)      acc = window_safe<true , ZV>(s01, s2q, o01, o2v, ws1d, base, gx, gy);\
        else if (s_hasZ) acc = window_safe<false, ZV>(s01, s2q, o01, o2v, ws1d, base, gx, gy);\
        else if (hasOOB) acc = window_fast<true , ZV>(s01, s2q, o01, o2v, base, gx, gy);    \
        else             acc = window_fast<false, ZV>(s01, s2q, o01, o2v, base, gx, gy);
    if (threadIdx.z == 0) { DISPATCH(0) }
    else                  { DISPATCH(1) }
    #undef DISPATCH

    red[tid] = acc;
    __syncthreads();
    #pragma unroll
    for (int s = NTHR / 2; s > 0; s >>= 1) {
        if (tid < s) red[tid] += red[tid + s];
        __syncthreads();
    }

    const int bid = blockIdx.y * gridDim.x + blockIdx.x;
    if (tid == 0) {
        g_part[bid] = red[0];
        __threadfence();
        unsigned old = atomicAdd(&g_counter, 1u);
        s_last = (old == (unsigned)(NBLK - 1)) ? 1 : 0;
    }
    __syncthreads();

    // Last block: deterministic fp64 finalize (fixed index order).
    if (s_last) {
        double s = 0.0;
        for (int i = tid; i < NBLK; i += NTHR) s += (double)__ldcg(&g_part[i]);
        rd[tid] = s;
        __syncthreads();
        #pragma unroll
        for (int k = NTHR / 2; k > 0; k >>= 1) {
            if (tid < k) rd[tid] += rd[tid + k];
            __syncthreads();
        }
        if (tid == 0) {
            const double scale = 1.0 / ((double)HH * (double)WW) / (double)(WSR * WSR);
            out[0] = (float)(rd[0] * scale);
            g_counter = 0;   // reset for next graph replay
        }
    }
}

extern "C" void kernel_launch(void* const* d_in, const int* in_sizes, int n_in,
                              void* d_out, int out_size)
{
    (void)in_sizes; (void)n_in; (void)out_size;
    const float* orig = (const float*)d_in[0];   // original_images (1,3,224,224)
    const float* smv  = (const float*)d_in[1];   // smooth_images   (1,3,224,224)
    float* out = (float*)d_out;

    mask_kernel<<<NPIX / 128, 128>>>(orig, smv);

    dim3 grid(GXB, GYB);
    dim3 blk(TX, TY, NZ);
    loss_kernel<<<grid, blk>>>(orig, smv, out);
}